// round 2
// baseline (speedup 1.0000x reference)
#include <cuda_runtime.h>

// BiAttention (BiDAF) layer: N=64, T=1024, J=64, D2=200.
// G = concat([H, U_, H*U_, H*H_], -1) -> (64, 1024, 800) fp32.

#define NEGV (-10000000.0f)

__device__ float g_Smax[64 * 1024];
__device__ float g_Hbar[64 * 200];

typedef unsigned long long ull;

// ---- shared layout (floats) ----
// U stored chunk-swizzled: offset(d) = (d>>3)*12 + (d&7), row stride 300.
#define UO_STRIDE 300
#define PS_STRIDE 68
#define OFF_UO   0                      // 64*300  = 19200
#define OFF_PS   19200                  // 128*68  = 8704
#define OFF_UWU  27904                  // 64
#define OFF_QM   27968                  // 64
#define OFF_W    28032                  // 600
#define SMEM_FLOATS 28640
#define SMEM_BYTES  (SMEM_FLOATS * 4)   // 114560

__device__ __forceinline__ void fma2(ull& acc, ull a, ull b) {
    asm("fma.rn.f32x2 %0, %1, %2, %0;" : "+l"(acc) : "l"(a), "l"(b));
}
__device__ __forceinline__ ull mul2(ull a, ull b) {
    ull r; asm("mul.rn.f32x2 %0, %1, %2;" : "=l"(r) : "l"(a), "l"(b)); return r;
}
__device__ __forceinline__ ull dup2(float x) {
    ull r; unsigned xi = __float_as_uint(x);
    asm("mov.b64 %0, {%1, %1};" : "=l"(r) : "r"(xi));
    return r;
}
__device__ __forceinline__ float lo32(ull v) { return __uint_as_float((unsigned)v); }
__device__ __forceinline__ float hi32(ull v) { return __uint_as_float((unsigned)(v >> 32)); }

union F4U2 { float4 f; ull u[2]; };

__global__ void __launch_bounds__(512, 1)
bi_attn_main(const float* __restrict__ H, const float* __restrict__ U,
             const float* __restrict__ q_mask, const float* __restrict__ wv,
             const float* __restrict__ bptr, float* __restrict__ G)
{
    extern __shared__ float sm[];
    float* sUo  = sm + OFF_UO;
    float* sPs  = sm + OFF_PS;
    float* sUwu = sm + OFF_UWU;
    float* sQm  = sm + OFF_QM;
    float* sW   = sm + OFF_W;

    const int tid = threadIdx.x;
    const int n   = blockIdx.y;
    const int m0  = blockIdx.x * 128;

    for (int i = tid; i < 600; i += 512) sW[i] = wv[i];
    if (tid < 64) sQm[tid] = q_mask[n * 64 + tid];
    __syncthreads();

    const float bval = bptr[0];

    // ---- stage U into chunk-swizzled smem + uwu = u . w_u ----
    {
        const int j  = tid >> 3;       // 0..63
        const int kg = tid & 7;
        const float* urow = U + (size_t)(n * 64 + j) * 200;
        float uwu = 0.f;
        #pragma unroll
        for (int c = kg; c < 50; c += 8) {
            float4 u4  = *(const float4*)(urow + c * 4);
            float4 wu4 = *(const float4*)(sW + 200 + c * 4);
            uwu += u4.x * wu4.x + u4.y * wu4.y + u4.z * wu4.z + u4.w * wu4.w;
            const int off = (c >> 1) * 12 + (c & 1) * 4;
            *(float4*)(sUo + j * UO_STRIDE + off) = u4;
        }
        uwu += __shfl_xor_sync(0xffffffffu, uwu, 1);
        uwu += __shfl_xor_sync(0xffffffffu, uwu, 2);
        uwu += __shfl_xor_sync(0xffffffffu, uwu, 4);
        if (kg == 0) sUwu[j] = uwu;
    }
    __syncthreads();

    const int tm = tid >> 3;     // 0..63 -> rows r0=tm*2, r0+1
    const int tj = tid & 7;      // 0..7  -> cols j = tj + 8*jj
    const int r0 = tm * 2;

    const float* h0p = H + (size_t)(n * 1024 + m0 + r0) * 200;
    const float* h1p = h0p + 200;
    const float* bBase = sUo + tj * UO_STRIDE;

    // ---- Phase A: S = (H*w_hu) @ U^T + rowdots, all f32x2 ----
    ull acc[2][8];
    #pragma unroll
    for (int i = 0; i < 2; i++)
        #pragma unroll
        for (int jj = 0; jj < 8; jj++) acc[i][jj] = 0ull;
    ull hwh2[2] = {0ull, 0ull};

    #pragma unroll 1
    for (int c = 0; c < 25; c++) {
        #pragma unroll
        for (int half = 0; half < 2; half++) {
            const int k  = c * 8  + half * 4;
            const int ko = c * 12 + half * 4;
            F4U2 h0, h1, wh, whu;
            h0.f  = *(const float4*)(h0p + k);
            h1.f  = *(const float4*)(h1p + k);
            wh.f  = *(const float4*)(sW + k);
            whu.f = *(const float4*)(sW + 400 + k);
            fma2(hwh2[0], h0.u[0], wh.u[0]);
            fma2(hwh2[0], h0.u[1], wh.u[1]);
            fma2(hwh2[1], h1.u[0], wh.u[0]);
            fma2(hwh2[1], h1.u[1], wh.u[1]);
            const ull a0lo = mul2(h0.u[0], whu.u[0]);
            const ull a0hi = mul2(h0.u[1], whu.u[1]);
            const ull a1lo = mul2(h1.u[0], whu.u[0]);
            const ull a1hi = mul2(h1.u[1], whu.u[1]);
            #pragma unroll
            for (int jj = 0; jj < 8; jj++) {
                F4U2 b; b.f = *(const float4*)(bBase + jj * (8 * UO_STRIDE) + ko);
                fma2(acc[0][jj], a0lo, b.u[0]);
                fma2(acc[0][jj], a0hi, b.u[1]);
                fma2(acc[1][jj], a1lo, b.u[0]);
                fma2(acc[1][jj], a1hi, b.u[1]);
            }
        }
    }

    // ---- Phase B: masked softmax over j, store P row-major ----
    #pragma unroll 1
    for (int i = 0; i < 2; i++) {
        const int m = r0 + i;
        const float hwh = lo32(hwh2[i]) + hi32(hwh2[i]);
        float vmv[8], qv[8];
        float mx = -3.4e38f, smx = -3.4e38f;
        #pragma unroll
        for (int jj = 0; jj < 8; jj++) {
            const int j = tj + 8 * jj;
            const ull v = acc[i][jj];
            const float s = lo32(v) + hi32(v) + hwh + sUwu[j] + bval;
            const float q = sQm[j];
            const float vm = s * q;
            vmv[jj] = vm; qv[jj] = q;
            mx  = fmaxf(mx, vm);
            smx = fmaxf(smx, (q != 0.f) ? s : NEGV);
        }
        mx  = fmaxf(mx,  __shfl_xor_sync(0xffffffffu, mx, 1));
        mx  = fmaxf(mx,  __shfl_xor_sync(0xffffffffu, mx, 2));
        mx  = fmaxf(mx,  __shfl_xor_sync(0xffffffffu, mx, 4));
        smx = fmaxf(smx, __shfl_xor_sync(0xffffffffu, smx, 1));
        smx = fmaxf(smx, __shfl_xor_sync(0xffffffffu, smx, 2));
        smx = fmaxf(smx, __shfl_xor_sync(0xffffffffu, smx, 4));
        float E = 0.f, M = 0.f, ev[8];
        #pragma unroll
        for (int jj = 0; jj < 8; jj++) {
            const float e = __expf(vmv[jj] - mx);
            ev[jj] = e; E += e; M += e * qv[jj];
        }
        E += __shfl_xor_sync(0xffffffffu, E, 1);
        E += __shfl_xor_sync(0xffffffffu, E, 2);
        E += __shfl_xor_sync(0xffffffffu, E, 4);
        M += __shfl_xor_sync(0xffffffffu, M, 1);
        M += __shfl_xor_sync(0xffffffffu, M, 2);
        M += __shfl_xor_sync(0xffffffffu, M, 4);
        const float inv = 1.0f / (M + 1e-13f * E);
        #pragma unroll
        for (int jj = 0; jj < 8; jj++)
            sPs[m * PS_STRIDE + tj + 8 * jj] = ev[jj] * qv[jj] * inv;
        if (tj == 0) g_Smax[(n << 10) + m0 + m] = smx;
    }
    __syncthreads();

    // ---- Phase C: U_ = P @ U ; write G[:,:,0:600] ----
    const float* ps0 = sPs + r0 * PS_STRIDE;
    const float* ps1 = ps0 + PS_STRIDE;
    const float* Hr0 = h0p;
    float*       Gr0 = G + (size_t)(n * 1024 + m0 + r0) * 800;

    #pragma unroll 1
    for (int pass = 0; pass < 4; pass++) {
        const int chunk = pass * 8 + tj;          // 0..31, valid < 25
        const bool valid = (chunk < 25);
        const int d0   = valid ? chunk * 8  : 0;
        const int uoff = valid ? chunk * 12 : 0;
        const float* uc = sUo + uoff;

        ull acc0[4], acc1[4];
        #pragma unroll
        for (int i = 0; i < 4; i++) { acc0[i] = 0ull; acc1[i] = 0ull; }

        #pragma unroll 1
        for (int j = 0; j < 64; j += 4) {
            F4U2 p0, p1;
            p0.f = *(const float4*)(ps0 + j);
            p1.f = *(const float4*)(ps1 + j);
            const float* pa0 = (const float*)&p0.f;
            const float* pa1 = (const float*)&p1.f;
            #pragma unroll
            for (int q = 0; q < 4; q++) {
                const float* up = uc + (j + q) * UO_STRIDE;
                F4U2 b0, b1;
                b0.f = *(const float4*)(up);
                b1.f = *(const float4*)(up + 4);
                const ull dp0 = dup2(pa0[q]);
                const ull dp1 = dup2(pa1[q]);
                fma2(acc0[0], dp0, b0.u[0]); fma2(acc0[1], dp0, b0.u[1]);
                fma2(acc0[2], dp0, b1.u[0]); fma2(acc0[3], dp0, b1.u[1]);
                fma2(acc1[0], dp1, b0.u[0]); fma2(acc1[1], dp1, b0.u[1]);
                fma2(acc1[2], dp1, b1.u[0]); fma2(acc1[3], dp1, b1.u[1]);
            }
        }

        if (valid) {
            #pragma unroll
            for (int i = 0; i < 2; i++) {
                const ull* A = i ? acc1 : acc0;
                float4 uA, uB;
                uA.x = lo32(A[0]); uA.y = hi32(A[0]); uA.z = lo32(A[1]); uA.w = hi32(A[1]);
                uB.x = lo32(A[2]); uB.y = hi32(A[2]); uB.z = lo32(A[3]); uB.w = hi32(A[3]);
                const float4 hA = *(const float4*)(Hr0 + i * 200 + d0);
                const float4 hB = *(const float4*)(Hr0 + i * 200 + d0 + 4);
                float* gp = Gr0 + (size_t)i * 800;
                *(float4*)(gp + d0)           = hA;
                *(float4*)(gp + d0 + 4)       = hB;
                *(float4*)(gp + 200 + d0)     = uA;
                *(float4*)(gp + 200 + d0 + 4) = uB;
                float4 mA, mB;
                mA.x = hA.x * uA.x; mA.y = hA.y * uA.y; mA.z = hA.z * uA.z; mA.w = hA.w * uA.w;
                mB.x = hB.x * uB.x; mB.y = hB.y * uB.y; mB.z = hB.z * uB.z; mB.w = hB.w * uB.w;
                *(float4*)(gp + 400 + d0)     = mA;
                *(float4*)(gp + 400 + d0 + 4) = mB;
            }
        }
    }
}

// ---- kernel 2: a = masked_softmax(S_max, c_mask); Hbar = a @ H ----
__global__ void __launch_bounds__(256)
bi_attn_ctx(const float* __restrict__ H, const float* __restrict__ c_mask)
{
    __shared__ float sa[1024];
    __shared__ float redA[8], redB[8], redC[8];
    __shared__ float part[8][208];
    const int n = blockIdx.x, tid = threadIdx.x;
    const int wid = tid >> 5, lane = tid & 31;

    float vm[4], cm[4];
    float mx = -3.4e38f;
    #pragma unroll
    for (int r = 0; r < 4; r++) {
        const int t = tid + 256 * r;
        const float c = c_mask[n * 1024 + t];
        const float v = g_Smax[n * 1024 + t] * c;
        vm[r] = v; cm[r] = c;
        mx = fmaxf(mx, v);
    }
    #pragma unroll
    for (int o = 16; o > 0; o >>= 1) mx = fmaxf(mx, __shfl_xor_sync(0xffffffffu, mx, o));
    if (lane == 0) redA[wid] = mx;
    __syncthreads();
    mx = redA[0];
    #pragma unroll
    for (int i = 1; i < 8; i++) mx = fmaxf(mx, redA[i]);

    float E = 0.f, M = 0.f, ev[4];
    #pragma unroll
    for (int r = 0; r < 4; r++) {
        const float e = __expf(vm[r] - mx);
        ev[r] = e; E += e; M += e * cm[r];
    }
    #pragma unroll
    for (int o = 16; o > 0; o >>= 1) {
        E += __shfl_xor_sync(0xffffffffu, E, o);
        M += __shfl_xor_sync(0xffffffffu, M, o);
    }
    if (lane == 0) { redB[wid] = E; redC[wid] = M; }
    __syncthreads();
    E = 0.f; M = 0.f;
    #pragma unroll
    for (int i = 0; i < 8; i++) { E += redB[i]; M += redC[i]; }
    const float inv = 1.0f / (M + 1e-13f * E);
    #pragma unroll
    for (int r = 0; r < 4; r++) sa[tid + 256 * r] = ev[r] * cm[r] * inv;
    __syncthreads();

    // Hbar: warp w covers t in [w*128, w*128+128), lanes own d slices.
    const int d0v = lane * 4;
    const int d1v = 128 + lane * 4;
    const bool v1 = (lane < 18);
    float4 a0 = {0.f, 0.f, 0.f, 0.f}, a1 = {0.f, 0.f, 0.f, 0.f};
    const float* hb = H + (size_t)n * 204800;
    #pragma unroll 4
    for (int t = wid * 128; t < wid * 128 + 128; t++) {
        const float av = sa[t];
        const float* hr = hb + (size_t)t * 200;
        const float4 h0 = *(const float4*)(hr + d0v);
        a0.x += av * h0.x; a0.y += av * h0.y; a0.z += av * h0.z; a0.w += av * h0.w;
        if (v1) {
            const float4 h1 = *(const float4*)(hr + d1v);
            a1.x += av * h1.x; a1.y += av * h1.y; a1.z += av * h1.z; a1.w += av * h1.w;
        }
    }
    *(float4*)(&part[wid][d0v]) = a0;
    if (v1) *(float4*)(&part[wid][d1v]) = a1;
    __syncthreads();

    if (tid < 200) {
        float s = 0.f;
        #pragma unroll
        for (int w = 0; w < 8; w++) s += part[w][tid];
        g_Hbar[n * 200 + tid] = s;
    }
}

// ---- kernel 3: G[:,:,600:800] = H * Hbar ----
__global__ void __launch_bounds__(256)
bi_attn_hh(const float* __restrict__ H, float* __restrict__ G)
{
    const int idx = blockIdx.x * 256 + threadIdx.x;   // < 64*1024*50
    const int r = idx / 50;
    const int c = idx - r * 50;
    const int n = r >> 10;
    const float4 h4 = *(const float4*)(H + (size_t)r * 200 + c * 4);
    const float4 hb = *(const float4*)(g_Hbar + n * 200 + c * 4);
    float4 o;
    o.x = h4.x * hb.x; o.y = h4.y * hb.y; o.z = h4.z * hb.z; o.w = h4.w * hb.w;
    *(float4*)(G + (size_t)r * 800 + 600 + c * 4) = o;
}

extern "C" void kernel_launch(void* const* d_in, const int* in_sizes, int n_in,
                              void* d_out, int out_size)
{
    const float* H      = (const float*)d_in[0];
    const float* U      = (const float*)d_in[1];
    const float* c_mask = (const float*)d_in[2];
    const float* q_mask = (const float*)d_in[3];
    const float* w      = (const float*)d_in[4];
    const float* b      = (const float*)d_in[5];
    float* G = (float*)d_out;

    cudaFuncSetAttribute(bi_attn_main, cudaFuncAttributeMaxDynamicSharedMemorySize, SMEM_BYTES);

    dim3 g1(8, 64);
    bi_attn_main<<<g1, 512, SMEM_BYTES>>>(H, U, q_mask, w, b, G);
    bi_attn_ctx<<<64, 256>>>(H, c_mask);
    bi_attn_hh<<<(64 * 1024 * 50) / 256, 256>>>(H, G);
}

// round 3
// speedup vs baseline: 1.0677x; 1.0677x over previous
#include <cuda_runtime.h>

// BiAttention (BiDAF): N=64, T=1024, J=64, D2=200.
// G = concat([H, U_, H*U_, H*H_], -1) -> (64, 1024, 800) fp32.

#define NEGV (-10000000.0f)

__device__ float g_Smax[64 * 1024];
__device__ float g_Hbar[64 * 200];

typedef unsigned long long ull;

// ---- shared layout (floats), stride 204 (bank-clean for our patterns) ----
#define SH        204
#define PD_STRIDE 136
#define OFF_H     0          // 128*204 = 26112 ; aliased by sPd (128*136=17408) after phase A
#define OFF_U     26112      // 64*204  = 13056
#define OFF_HWH   39168      // 128
#define OFF_UWU   39296      // 64
#define OFF_QM    39360      // 64
#define OFF_W     39424      // 600
#define SMEM_FLOATS 40032
#define SMEM_BYTES  (SMEM_FLOATS * 4)   // 160128

__device__ __forceinline__ void fma2(ull& acc, ull a, ull b) {
    asm("fma.rn.f32x2 %0, %1, %2, %0;" : "+l"(acc) : "l"(a), "l"(b));
}
__device__ __forceinline__ float lo32(ull v) { return __uint_as_float((unsigned)v); }
__device__ __forceinline__ float hi32(ull v) { return __uint_as_float((unsigned)(v >> 32)); }

union F4U2 { float4 f; ull u[2]; };

__global__ void __launch_bounds__(512, 1)
bi_attn_main(const float* __restrict__ H, const float* __restrict__ U,
             const float* __restrict__ q_mask, const float* __restrict__ wv,
             const float* __restrict__ bptr, float* __restrict__ G)
{
    extern __shared__ float sm[];
    float* sH   = sm + OFF_H;    // scaled H tile [128][204] (h * w_hu)
    float* sPd  = sm + OFF_H;    // ALIAS: duplicated P [128][136] = {p,p} pairs
    float* sU   = sm + OFF_U;    // U tile [64][204]
    float* sHwh = sm + OFF_HWH;
    float* sUwu = sm + OFF_UWU;
    float* sQm  = sm + OFF_QM;
    float* sW   = sm + OFF_W;

    const int tid = threadIdx.x;
    const int n   = blockIdx.y;
    const int m0  = blockIdx.x * 128;

    for (int i = tid; i < 600; i += 512) sW[i] = wv[i];
    if (tid < 64) sQm[tid] = q_mask[n * 64 + tid];
    __syncthreads();

    const float bval = bptr[0];

    // ---- stage U (raw) + uwu = u . w_u : 8 lanes per j-row ----
    {
        const int j  = tid >> 3;
        const int kg = tid & 7;
        const float* urow = U + (size_t)(n * 64 + j) * 200;
        float uwu = 0.f;
        #pragma unroll
        for (int c = kg; c < 50; c += 8) {
            float4 u4  = *(const float4*)(urow + c * 4);
            float4 wu4 = *(const float4*)(sW + 200 + c * 4);
            uwu += u4.x * wu4.x + u4.y * wu4.y + u4.z * wu4.z + u4.w * wu4.w;
            *(float4*)(sU + j * SH + c * 4) = u4;
        }
        uwu += __shfl_xor_sync(0xffffffffu, uwu, 1);
        uwu += __shfl_xor_sync(0xffffffffu, uwu, 2);
        uwu += __shfl_xor_sync(0xffffffffu, uwu, 4);
        if (kg == 0) sUwu[j] = uwu;
    }
    // ---- stage H scaled by w_hu + hwh = h . w_h : 4 lanes per row ----
    {
        const int row = tid >> 2;      // 0..127
        const int kg  = tid & 3;
        const float* hrow = H + (size_t)(n * 1024 + m0 + row) * 200;
        float hwh = 0.f;
        #pragma unroll
        for (int c = kg; c < 50; c += 4) {
            float4 h4   = *(const float4*)(hrow + c * 4);
            float4 wh4  = *(const float4*)(sW + c * 4);
            float4 whu4 = *(const float4*)(sW + 400 + c * 4);
            hwh += h4.x * wh4.x + h4.y * wh4.y + h4.z * wh4.z + h4.w * wh4.w;
            float4 hs;
            hs.x = h4.x * whu4.x; hs.y = h4.y * whu4.y;
            hs.z = h4.z * whu4.z; hs.w = h4.w * whu4.w;
            *(float4*)(sH + row * SH + c * 4) = hs;
        }
        hwh += __shfl_xor_sync(0xffffffffu, hwh, 1);
        hwh += __shfl_xor_sync(0xffffffffu, hwh, 2);
        if (kg == 0) sHwh[row] = hwh;
    }
    __syncthreads();

    const int tm = tid >> 3;     // 0..63 -> rows r0 = tm*2, r0+1
    const int tj = tid & 7;      // 0..7  -> cols j = tj + 8*jj
    const int r0 = tm * 2;

    // ---- Phase A: S-tile GEMM, LDS.128 over 4k, acc 2m x 8j ----
    ull acc[2][8];
    #pragma unroll
    for (int i = 0; i < 2; i++)
        #pragma unroll
        for (int jj = 0; jj < 8; jj++) acc[i][jj] = 0ull;

    const float* aBase = sH + r0 * SH;
    const float* bBase = sU + tj * SH;

    #pragma unroll 2
    for (int kc = 0; kc < 50; kc++) {
        const int k = kc * 4;
        F4U2 a0, a1;
        a0.f = *(const float4*)(aBase + k);
        a1.f = *(const float4*)(aBase + SH + k);
        F4U2 b[8];
        #pragma unroll
        for (int jj = 0; jj < 8; jj++)
            b[jj].f = *(const float4*)(bBase + jj * (8 * SH) + k);
        #pragma unroll
        for (int jj = 0; jj < 8; jj++) {
            fma2(acc[0][jj], a0.u[0], b[jj].u[0]);
            fma2(acc[0][jj], a0.u[1], b[jj].u[1]);
            fma2(acc[1][jj], a1.u[0], b[jj].u[0]);
            fma2(acc[1][jj], a1.u[1], b[jj].u[1]);
        }
    }

    // ---- Phase B: masked softmax over j (in registers) ----
    float pv[2][8];
    #pragma unroll
    for (int i = 0; i < 2; i++) {
        const int m = r0 + i;
        const float hwh = sHwh[m];
        float vmv[8], qv[8];
        float mx = -3.4e38f, smx = -3.4e38f;
        #pragma unroll
        for (int jj = 0; jj < 8; jj++) {
            const int j = tj + 8 * jj;
            const ull v = acc[i][jj];
            const float s = lo32(v) + hi32(v) + hwh + sUwu[j] + bval;
            const float q = sQm[j];
            const float vm = s * q;
            vmv[jj] = vm; qv[jj] = q;
            mx  = fmaxf(mx, vm);
            smx = fmaxf(smx, (q != 0.f) ? s : NEGV);
        }
        mx  = fmaxf(mx,  __shfl_xor_sync(0xffffffffu, mx, 1));
        mx  = fmaxf(mx,  __shfl_xor_sync(0xffffffffu, mx, 2));
        mx  = fmaxf(mx,  __shfl_xor_sync(0xffffffffu, mx, 4));
        smx = fmaxf(smx, __shfl_xor_sync(0xffffffffu, smx, 1));
        smx = fmaxf(smx, __shfl_xor_sync(0xffffffffu, smx, 2));
        smx = fmaxf(smx, __shfl_xor_sync(0xffffffffu, smx, 4));
        float E = 0.f, M = 0.f, ev[8];
        #pragma unroll
        for (int jj = 0; jj < 8; jj++) {
            const float e = __expf(vmv[jj] - mx);
            ev[jj] = e; E += e; M += e * qv[jj];
        }
        E += __shfl_xor_sync(0xffffffffu, E, 1);
        E += __shfl_xor_sync(0xffffffffu, E, 2);
        E += __shfl_xor_sync(0xffffffffu, E, 4);
        M += __shfl_xor_sync(0xffffffffu, M, 1);
        M += __shfl_xor_sync(0xffffffffu, M, 2);
        M += __shfl_xor_sync(0xffffffffu, M, 4);
        const float inv = 1.0f / (M + 1e-13f * E);
        #pragma unroll
        for (int jj = 0; jj < 8; jj++) pv[i][jj] = ev[jj] * qv[jj] * inv;
        if (tj == 0) g_Smax[(n << 10) + m0 + m] = smx;
    }

    __syncthreads();   // everyone done reading sH (phase A)

    // store P duplicated: sPd[m][2j], [2j+1] = p  (enables mov-free fma2 in C)
    #pragma unroll
    for (int i = 0; i < 2; i++) {
        float* base = sPd + (size_t)(r0 + i) * PD_STRIDE;
        #pragma unroll
        for (int jj = 0; jj < 8; jj++) {
            const int j = tj + 8 * jj;
            float2 d; d.x = pv[i][jj]; d.y = pv[i][jj];
            *(float2*)(base + 2 * j) = d;
        }
    }
    __syncthreads();

    // ---- Phase C: U_ = P @ U ; write G[:,:,0:600] ----
    const float* Hrow = H + (size_t)(n * 1024 + m0 + r0) * 200;
    float*       Grow = G + (size_t)(n * 1024 + m0 + r0) * 800;
    const float* pd0 = sPd + (size_t)r0 * PD_STRIDE;
    const float* pd1 = pd0 + PD_STRIDE;

    #pragma unroll 1
    for (int pass = 0; pass < 7; pass++) {
        const int chunk = pass * 8 + tj;          // 0..55, valid < 50
        const bool valid = (chunk < 50);
        const int d0 = valid ? chunk * 4 : 0;
        const float* uc = sU + d0;

        ull acc0[2], acc1[2];
        acc0[0] = acc0[1] = acc1[0] = acc1[1] = 0ull;

        #pragma unroll 4
        for (int j = 0; j < 64; j += 4) {
            F4U2 P0A, P0B, P1A, P1B;
            P0A.f = *(const float4*)(pd0 + 2 * j);
            P0B.f = *(const float4*)(pd0 + 2 * j + 4);
            P1A.f = *(const float4*)(pd1 + 2 * j);
            P1B.f = *(const float4*)(pd1 + 2 * j + 4);
            F4U2 b0, b1, b2, b3;
            b0.f = *(const float4*)(uc + (j + 0) * SH);
            b1.f = *(const float4*)(uc + (j + 1) * SH);
            b2.f = *(const float4*)(uc + (j + 2) * SH);
            b3.f = *(const float4*)(uc + (j + 3) * SH);
            fma2(acc0[0], P0A.u[0], b0.u[0]); fma2(acc0[1], P0A.u[0], b0.u[1]);
            fma2(acc1[0], P1A.u[0], b0.u[0]); fma2(acc1[1], P1A.u[0], b0.u[1]);
            fma2(acc0[0], P0A.u[1], b1.u[0]); fma2(acc0[1], P0A.u[1], b1.u[1]);
            fma2(acc1[0], P1A.u[1], b1.u[0]); fma2(acc1[1], P1A.u[1], b1.u[1]);
            fma2(acc0[0], P0B.u[0], b2.u[0]); fma2(acc0[1], P0B.u[0], b2.u[1]);
            fma2(acc1[0], P1B.u[0], b2.u[0]); fma2(acc1[1], P1B.u[0], b2.u[1]);
            fma2(acc0[0], P0B.u[1], b3.u[0]); fma2(acc0[1], P0B.u[1], b3.u[1]);
            fma2(acc1[0], P1B.u[1], b3.u[0]); fma2(acc1[1], P1B.u[1], b3.u[1]);
        }

        if (valid) {
            #pragma unroll
            for (int i = 0; i < 2; i++) {
                const ull* A = i ? acc1 : acc0;
                float4 u4;
                u4.x = lo32(A[0]); u4.y = hi32(A[0]);
                u4.z = lo32(A[1]); u4.w = hi32(A[1]);
                const float4 h4 = *(const float4*)(Hrow + i * 200 + d0);
                float* gp = Grow + (size_t)i * 800;
                *(float4*)(gp + d0)       = h4;
                *(float4*)(gp + 200 + d0) = u4;
                float4 m4;
                m4.x = h4.x * u4.x; m4.y = h4.y * u4.y;
                m4.z = h4.z * u4.z; m4.w = h4.w * u4.w;
                *(float4*)(gp + 400 + d0) = m4;
            }
        }
    }
}

// ---- kernel 2: a = masked_softmax(S_max, c_mask); Hbar = a @ H ----
__global__ void __launch_bounds__(256)
bi_attn_ctx(const float* __restrict__ H, const float* __restrict__ c_mask)
{
    __shared__ float sa[1024];
    __shared__ float redA[8], redB[8], redC[8];
    __shared__ float part[8][208];
    const int n = blockIdx.x, tid = threadIdx.x;
    const int wid = tid >> 5, lane = tid & 31;

    float vm[4], cm[4];
    float mx = -3.4e38f;
    #pragma unroll
    for (int r = 0; r < 4; r++) {
        const int t = tid + 256 * r;
        const float c = c_mask[n * 1024 + t];
        const float v = g_Smax[n * 1024 + t] * c;
        vm[r] = v; cm[r] = c;
        mx = fmaxf(mx, v);
    }
    #pragma unroll
    for (int o = 16; o > 0; o >>= 1) mx = fmaxf(mx, __shfl_xor_sync(0xffffffffu, mx, o));
    if (lane == 0) redA[wid] = mx;
    __syncthreads();
    mx = redA[0];
    #pragma unroll
    for (int i = 1; i < 8; i++) mx = fmaxf(mx, redA[i]);

    float E = 0.f, M = 0.f, ev[4];
    #pragma unroll
    for (int r = 0; r < 4; r++) {
        const float e = __expf(vm[r] - mx);
        ev[r] = e; E += e; M += e * cm[r];
    }
    #pragma unroll
    for (int o = 16; o > 0; o >>= 1) {
        E += __shfl_xor_sync(0xffffffffu, E, o);
        M += __shfl_xor_sync(0xffffffffu, M, o);
    }
    if (lane == 0) { redB[wid] = E; redC[wid] = M; }
    __syncthreads();
    E = 0.f; M = 0.f;
    #pragma unroll
    for (int i = 0; i < 8; i++) { E += redB[i]; M += redC[i]; }
    const float inv = 1.0f / (M + 1e-13f * E);
    #pragma unroll
    for (int r = 0; r < 4; r++) sa[tid + 256 * r] = ev[r] * cm[r] * inv;
    __syncthreads();

    const int d0v = lane * 4;
    const int d1v = 128 + lane * 4;
    const bool v1 = (lane < 18);
    float4 a0 = {0.f, 0.f, 0.f, 0.f}, a1 = {0.f, 0.f, 0.f, 0.f};
    const float* hb = H + (size_t)n * 204800;
    #pragma unroll 4
    for (int t = wid * 128; t < wid * 128 + 128; t++) {
        const float av = sa[t];
        const float* hr = hb + (size_t)t * 200;
        const float4 h0 = *(const float4*)(hr + d0v);
        a0.x += av * h0.x; a0.y += av * h0.y; a0.z += av * h0.z; a0.w += av * h0.w;
        if (v1) {
            const float4 h1 = *(const float4*)(hr + d1v);
            a1.x += av * h1.x; a1.y += av * h1.y; a1.z += av * h1.z; a1.w += av * h1.w;
        }
    }
    *(float4*)(&part[wid][d0v]) = a0;
    if (v1) *(float4*)(&part[wid][d1v]) = a1;
    __syncthreads();

    if (tid < 200) {
        float s = 0.f;
        #pragma unroll
        for (int w = 0; w < 8; w++) s += part[w][tid];
        g_Hbar[n * 200 + tid] = s;
    }
}

// ---- kernel 3: G[:,:,600:800] = H * Hbar ----
__global__ void __launch_bounds__(512)
bi_attn_hh(const float* __restrict__ H, float* __restrict__ G)
{
    const int idx = blockIdx.x * 512 + threadIdx.x;   // < 64*1024*50
    const int r = idx / 50;
    const int c = idx - r * 50;
    const int n = r >> 10;
    const float4 h4 = *(const float4*)(H + (size_t)r * 200 + c * 4);
    const float4 hb = *(const float4*)(g_Hbar + n * 200 + c * 4);
    float4 o;
    o.x = h4.x * hb.x; o.y = h4.y * hb.y; o.z = h4.z * hb.z; o.w = h4.w * hb.w;
    *(float4*)(G + (size_t)r * 800 + 600 + c * 4) = o;
}

extern "C" void kernel_launch(void* const* d_in, const int* in_sizes, int n_in,
                              void* d_out, int out_size)
{
    const float* H      = (const float*)d_in[0];
    const float* U      = (const float*)d_in[1];
    const float* c_mask = (const float*)d_in[2];
    const float* q_mask = (const float*)d_in[3];
    const float* w      = (const float*)d_in[4];
    const float* b      = (const float*)d_in[5];
    float* G = (float*)d_out;

    cudaFuncSetAttribute(bi_attn_main, cudaFuncAttributeMaxDynamicSharedMemorySize, SMEM_BYTES);

    dim3 g1(8, 64);
    bi_attn_main<<<g1, 512, SMEM_BYTES>>>(H, U, q_mask, w, b, G);
    bi_attn_ctx<<<64, 256>>>(H, c_mask);
    bi_attn_hh<<<(64 * 1024 * 50) / 512, 512>>>(H, G);
}

// round 4
// speedup vs baseline: 1.1276x; 1.0562x over previous
#include <cuda_runtime.h>

// BiAttention (BiDAF): N=64, T=1024, J=64, D2=200.
// G = concat([H, U_, H*U_, H*H_], -1) -> (64, 1024, 800) fp32.

#define NEGV (-10000000.0f)

__device__ float g_Smax[64 * 1024];

typedef unsigned long long ull;

// ---- shared layout (floats) ----
// sU  : U tile [64][204]  (full k, bank-clean: tj*204 % 32 = 12*tj distinct)
// sX  : region reused: H half-tile [128][108] (phase A), then P [128][68] (phase C)
#define SU   204
#define SXH  108
#define SPS  68
#define OFF_U    0
#define OFF_X    13056
#define OFF_HWH  26880
#define OFF_UWU  27008
#define OFF_QM   27072
#define OFF_W    27136
#define SMEM_FLOATS 27736
#define SMEM_BYTES  (SMEM_FLOATS * 4)   // 110944 -> 2 CTAs/SM

__device__ __forceinline__ void fma2(ull& acc, ull a, ull b) {
    asm("fma.rn.f32x2 %0, %1, %2, %0;" : "+l"(acc) : "l"(a), "l"(b));
}
__device__ __forceinline__ ull dup2(float x) {
    ull r; unsigned xi = __float_as_uint(x);
    asm("mov.b64 %0, {%1, %1};" : "=l"(r) : "r"(xi));
    return r;
}
__device__ __forceinline__ float lo32(ull v) { return __uint_as_float((unsigned)v); }
__device__ __forceinline__ float hi32(ull v) { return __uint_as_float((unsigned)(v >> 32)); }

union F4U2 { float4 f; ull u[2]; };

__global__ void __launch_bounds__(256, 2)
bi_attn_main(const float* __restrict__ H, const float* __restrict__ U,
             const float* __restrict__ q_mask, const float* __restrict__ wv,
             const float* __restrict__ bptr, float* __restrict__ G)
{
    extern __shared__ float sm[];
    float* sU   = sm + OFF_U;
    float* sH   = sm + OFF_X;    // H half-tile (phase A)
    float* sPs  = sm + OFF_X;    // ALIAS: P [128][68] (phase C)
    float* sHwh = sm + OFF_HWH;
    float* sUwu = sm + OFF_UWU;
    float* sQm  = sm + OFF_QM;
    float* sW   = sm + OFF_W;

    const int tid = threadIdx.x;
    const int n   = blockIdx.y;
    const int m0  = blockIdx.x * 128;

    for (int i = tid; i < 600; i += 256) sW[i] = wv[i];
    if (tid < 64) sQm[tid] = q_mask[n * 64 + tid];
    __syncthreads();

    const float bval = bptr[0];

    // ---- stage U full (k=0..200) + uwu : 4 lanes per j-row ----
    {
        const int j  = tid >> 2;
        const int kg = tid & 3;
        const float* urow = U + (size_t)(n * 64 + j) * 200;
        float uwu = 0.f;
        #pragma unroll
        for (int c = kg; c < 50; c += 4) {
            float4 u4  = *(const float4*)(urow + c * 4);
            float4 wu4 = *(const float4*)(sW + 200 + c * 4);
            uwu += u4.x * wu4.x + u4.y * wu4.y + u4.z * wu4.z + u4.w * wu4.w;
            *(float4*)(sU + j * SU + c * 4) = u4;
        }
        uwu += __shfl_xor_sync(0xffffffffu, uwu, 1);
        uwu += __shfl_xor_sync(0xffffffffu, uwu, 2);
        if (kg == 0) sUwu[j] = uwu;
    }

    // H staging setup: 2 lanes per row
    const int hrowi = tid >> 1;
    const int hkg   = tid & 1;
    const float* hrow = H + (size_t)(n * 1024 + m0 + hrowi) * 200;
    float hwh_acc = 0.f;

    // stage H half 0 (k in [0,100))
    #pragma unroll
    for (int c = hkg; c < 25; c += 2) {
        const int k = c * 4;
        float4 h4   = *(const float4*)(hrow + k);
        float4 wh4  = *(const float4*)(sW + k);
        float4 whu4 = *(const float4*)(sW + 400 + k);
        hwh_acc += h4.x * wh4.x + h4.y * wh4.y + h4.z * wh4.z + h4.w * wh4.w;
        float4 hs;
        hs.x = h4.x * whu4.x; hs.y = h4.y * whu4.y;
        hs.z = h4.z * whu4.z; hs.w = h4.w * whu4.w;
        *(float4*)(sH + hrowi * SXH + k) = hs;
    }
    __syncthreads();

    const int mg = tid >> 3;   // 0..31 -> rows mg*4 .. mg*4+3
    const int tj = tid & 7;    // 0..7  -> cols j = tj + 8*jj

    ull acc[4][8];
    #pragma unroll
    for (int i = 0; i < 4; i++)
        #pragma unroll
        for (int jj = 0; jj < 8; jj++) acc[i][jj] = 0ull;

    const float* aBase = sH + mg * 4 * SXH;
    const float* bBase = sU + tj * SU;

    // ---- GEMM half 0 ----
    #pragma unroll 1
    for (int kc = 0; kc < 25; kc++) {
        const int k = kc * 4;
        F4U2 a0, a1, a2, a3;
        a0.f = *(const float4*)(aBase + k);
        a1.f = *(const float4*)(aBase + SXH + k);
        a2.f = *(const float4*)(aBase + 2 * SXH + k);
        a3.f = *(const float4*)(aBase + 3 * SXH + k);
        #pragma unroll
        for (int g = 0; g < 2; g++) {
            F4U2 b[4];
            #pragma unroll
            for (int q = 0; q < 4; q++)
                b[q].f = *(const float4*)(bBase + (g * 4 + q) * (8 * SU) + k);
            #pragma unroll
            for (int q = 0; q < 4; q++) {
                const int jj = g * 4 + q;
                fma2(acc[0][jj], a0.u[0], b[q].u[0]); fma2(acc[0][jj], a0.u[1], b[q].u[1]);
                fma2(acc[1][jj], a1.u[0], b[q].u[0]); fma2(acc[1][jj], a1.u[1], b[q].u[1]);
                fma2(acc[2][jj], a2.u[0], b[q].u[0]); fma2(acc[2][jj], a2.u[1], b[q].u[1]);
                fma2(acc[3][jj], a3.u[0], b[q].u[0]); fma2(acc[3][jj], a3.u[1], b[q].u[1]);
            }
        }
    }
    __syncthreads();

    // stage H half 1 (k in [100,200)), finalize hwh
    #pragma unroll
    for (int c = hkg; c < 25; c += 2) {
        const int k = 100 + c * 4;
        float4 h4   = *(const float4*)(hrow + k);
        float4 wh4  = *(const float4*)(sW + k);
        float4 whu4 = *(const float4*)(sW + 400 + k);
        hwh_acc += h4.x * wh4.x + h4.y * wh4.y + h4.z * wh4.z + h4.w * wh4.w;
        float4 hs;
        hs.x = h4.x * whu4.x; hs.y = h4.y * whu4.y;
        hs.z = h4.z * whu4.z; hs.w = h4.w * whu4.w;
        *(float4*)(sH + hrowi * SXH + c * 4) = hs;
    }
    {
        float hv = hwh_acc + __shfl_xor_sync(0xffffffffu, hwh_acc, 1);
        if (hkg == 0) sHwh[hrowi] = hv;
    }
    __syncthreads();

    // ---- GEMM half 1 (B offset +100) ----
    #pragma unroll 1
    for (int kc = 0; kc < 25; kc++) {
        const int k = kc * 4;
        F4U2 a0, a1, a2, a3;
        a0.f = *(const float4*)(aBase + k);
        a1.f = *(const float4*)(aBase + SXH + k);
        a2.f = *(const float4*)(aBase + 2 * SXH + k);
        a3.f = *(const float4*)(aBase + 3 * SXH + k);
        #pragma unroll
        for (int g = 0; g < 2; g++) {
            F4U2 b[4];
            #pragma unroll
            for (int q = 0; q < 4; q++)
                b[q].f = *(const float4*)(bBase + 100 + (g * 4 + q) * (8 * SU) + k);
            #pragma unroll
            for (int q = 0; q < 4; q++) {
                const int jj = g * 4 + q;
                fma2(acc[0][jj], a0.u[0], b[q].u[0]); fma2(acc[0][jj], a0.u[1], b[q].u[1]);
                fma2(acc[1][jj], a1.u[0], b[q].u[0]); fma2(acc[1][jj], a1.u[1], b[q].u[1]);
                fma2(acc[2][jj], a2.u[0], b[q].u[0]); fma2(acc[2][jj], a2.u[1], b[q].u[1]);
                fma2(acc[3][jj], a3.u[0], b[q].u[0]); fma2(acc[3][jj], a3.u[1], b[q].u[1]);
            }
        }
    }
    __syncthreads();   // all reads of sH done; sHwh visible

    // ---- softmax over j for 4 rows; write P plain into sPs ----
    #pragma unroll 1
    for (int i = 0; i < 4; i++) {
        const int m = mg * 4 + i;
        const float hwh = sHwh[m];
        float vmv[8], qv[8];
        float mx = -3.4e38f, smx = -3.4e38f;
        #pragma unroll
        for (int jj = 0; jj < 8; jj++) {
            const int j = tj + 8 * jj;
            const ull v = acc[i][jj];
            const float s = lo32(v) + hi32(v) + hwh + sUwu[j] + bval;
            const float q = sQm[j];
            const float vm = s * q;
            vmv[jj] = vm; qv[jj] = q;
            mx  = fmaxf(mx, vm);
            smx = fmaxf(smx, (q != 0.f) ? s : NEGV);
        }
        mx  = fmaxf(mx,  __shfl_xor_sync(0xffffffffu, mx, 1));
        mx  = fmaxf(mx,  __shfl_xor_sync(0xffffffffu, mx, 2));
        mx  = fmaxf(mx,  __shfl_xor_sync(0xffffffffu, mx, 4));
        smx = fmaxf(smx, __shfl_xor_sync(0xffffffffu, smx, 1));
        smx = fmaxf(smx, __shfl_xor_sync(0xffffffffu, smx, 2));
        smx = fmaxf(smx, __shfl_xor_sync(0xffffffffu, smx, 4));
        float E = 0.f, M = 0.f, ev[8];
        #pragma unroll
        for (int jj = 0; jj < 8; jj++) {
            const float e = __expf(vmv[jj] - mx);
            ev[jj] = e; E += e; M += e * qv[jj];
        }
        E += __shfl_xor_sync(0xffffffffu, E, 1);
        E += __shfl_xor_sync(0xffffffffu, E, 2);
        E += __shfl_xor_sync(0xffffffffu, E, 4);
        M += __shfl_xor_sync(0xffffffffu, M, 1);
        M += __shfl_xor_sync(0xffffffffu, M, 2);
        M += __shfl_xor_sync(0xffffffffu, M, 4);
        const float inv = 1.0f / (M + 1e-13f * E);
        #pragma unroll
        for (int jj = 0; jj < 8; jj++)
            sPs[m * SPS + tj + 8 * jj] = ev[jj] * qv[jj] * inv;
        if (tj == 0) g_Smax[(n << 10) + m0 + m] = smx;
    }
    __syncthreads();

    // ---- Phase C: U_ = P @ U ; write G[:,:,0:600] ----
    // 8 rows per thread (rg), 8-float d-chunk per lane (dl), 2 passes.
    const int rg = tid >> 4;        // 0..15 -> rows rg*8 .. rg*8+7
    const int dl = tid & 15;        // 0..15 -> chunk = pass*16 + dl
    const float* pRow = sPs + rg * 8 * SPS;
    const float* HrowC = H + (size_t)(n * 1024 + m0 + rg * 8) * 200;
    float*       GrowC = G + (size_t)(n * 1024 + m0 + rg * 8) * 800;

    #pragma unroll 1
    for (int p = 0; p < 2; p++) {
        const int chunk = p * 16 + dl;
        const bool valid = (chunk < 25);
        const int d0 = valid ? chunk * 8 : 0;

        ull acc2[8][4];
        #pragma unroll
        for (int r = 0; r < 8; r++)
            #pragma unroll
            for (int u = 0; u < 4; u++) acc2[r][u] = 0ull;

        #pragma unroll 1
        for (int j = 0; j < 64; j += 4) {
            float4 P[8];
            #pragma unroll
            for (int r = 0; r < 8; r++)
                P[r] = *(const float4*)(pRow + r * SPS + j);
            #pragma unroll
            for (int q = 0; q < 4; q++) {
                const float* up = sU + (j + q) * SU + d0;
                F4U2 bA, bB;
                bA.f = *(const float4*)(up);
                bB.f = *(const float4*)(up + 4);
                const float* Pq = (const float*)P;
                #pragma unroll
                for (int r = 0; r < 8; r++) {
                    const ull d = dup2(Pq[r * 4 + q]);
                    fma2(acc2[r][0], d, bA.u[0]);
                    fma2(acc2[r][1], d, bA.u[1]);
                    fma2(acc2[r][2], d, bB.u[0]);
                    fma2(acc2[r][3], d, bB.u[1]);
                }
            }
        }

        if (valid) {
            #pragma unroll
            for (int r = 0; r < 8; r++) {
                float4 uA, uB;
                uA.x = lo32(acc2[r][0]); uA.y = hi32(acc2[r][0]);
                uA.z = lo32(acc2[r][1]); uA.w = hi32(acc2[r][1]);
                uB.x = lo32(acc2[r][2]); uB.y = hi32(acc2[r][2]);
                uB.z = lo32(acc2[r][3]); uB.w = hi32(acc2[r][3]);
                const float4 hA = *(const float4*)(HrowC + r * 200 + d0);
                const float4 hB = *(const float4*)(HrowC + r * 200 + d0 + 4);
                float* gp = GrowC + (size_t)r * 800;
                *(float4*)(gp + d0)           = hA;
                *(float4*)(gp + d0 + 4)       = hB;
                *(float4*)(gp + 200 + d0)     = uA;
                *(float4*)(gp + 200 + d0 + 4) = uB;
                float4 mA, mB;
                mA.x = hA.x * uA.x; mA.y = hA.y * uA.y; mA.z = hA.z * uA.z; mA.w = hA.w * uA.w;
                mB.x = hB.x * uB.x; mB.y = hB.y * uB.y; mB.z = hB.z * uB.z; mB.w = hB.w * uB.w;
                *(float4*)(gp + 400 + d0)     = mA;
                *(float4*)(gp + 400 + d0 + 4) = mB;
            }
        }
    }
}

// ---- fused tail: a = masked_softmax(S_max, c_mask); Hbar = a@H; G[...,600:800] = H*Hbar ----
__global__ void __launch_bounds__(512)
bi_attn_tail(const float* __restrict__ H, const float* __restrict__ c_mask,
             float* __restrict__ G)
{
    __shared__ float sa[1024];
    __shared__ float redA[16], redB[16], redC[16];
    __shared__ float part[16][208];
    __shared__ float hbar[200];
    const int n = blockIdx.x, tid = threadIdx.x;
    const int wid = tid >> 5, lane = tid & 31;

    float vm[2], cm[2];
    float mx = -3.4e38f;
    #pragma unroll
    for (int r = 0; r < 2; r++) {
        const int t = tid + 512 * r;
        const float c = c_mask[n * 1024 + t];
        const float v = g_Smax[n * 1024 + t] * c;
        vm[r] = v; cm[r] = c;
        mx = fmaxf(mx, v);
    }
    #pragma unroll
    for (int o = 16; o > 0; o >>= 1) mx = fmaxf(mx, __shfl_xor_sync(0xffffffffu, mx, o));
    if (lane == 0) redA[wid] = mx;
    __syncthreads();
    mx = redA[0];
    #pragma unroll
    for (int i = 1; i < 16; i++) mx = fmaxf(mx, redA[i]);

    float E = 0.f, M = 0.f, ev[2];
    #pragma unroll
    for (int r = 0; r < 2; r++) {
        const float e = __expf(vm[r] - mx);
        ev[r] = e; E += e; M += e * cm[r];
    }
    #pragma unroll
    for (int o = 16; o > 0; o >>= 1) {
        E += __shfl_xor_sync(0xffffffffu, E, o);
        M += __shfl_xor_sync(0xffffffffu, M, o);
    }
    if (lane == 0) { redB[wid] = E; redC[wid] = M; }
    __syncthreads();
    E = 0.f; M = 0.f;
    #pragma unroll
    for (int i = 0; i < 16; i++) { E += redB[i]; M += redC[i]; }
    const float inv = 1.0f / (M + 1e-13f * E);
    #pragma unroll
    for (int r = 0; r < 2; r++) sa[tid + 512 * r] = ev[r] * cm[r] * inv;
    __syncthreads();

    // Hbar: warp w covers t in [w*64, w*64+64); lanes own d-slices
    const int d0v = lane * 4;
    const int d1v = 128 + lane * 4;
    const bool v1 = (lane < 18);
    float4 a0 = {0.f, 0.f, 0.f, 0.f}, a1 = {0.f, 0.f, 0.f, 0.f};
    const float* hb = H + (size_t)n * 204800;
    #pragma unroll 4
    for (int t = wid * 64; t < wid * 64 + 64; t++) {
        const float av = sa[t];
        const float* hr = hb + (size_t)t * 200;
        const float4 h0 = *(const float4*)(hr + d0v);
        a0.x += av * h0.x; a0.y += av * h0.y; a0.z += av * h0.z; a0.w += av * h0.w;
        if (v1) {
            const float4 h1 = *(const float4*)(hr + d1v);
            a1.x += av * h1.x; a1.y += av * h1.y; a1.z += av * h1.z; a1.w += av * h1.w;
        }
    }
    *(float4*)(&part[wid][d0v]) = a0;
    if (v1) *(float4*)(&part[wid][d1v]) = a1;
    __syncthreads();

    if (tid < 200) {
        float s = 0.f;
        #pragma unroll
        for (int w = 0; w < 16; w++) s += part[w][tid];
        hbar[tid] = s;
    }
    __syncthreads();

    // product: G[n, t, 600:800] = H[n, t, :] * hbar
    #pragma unroll 1
    for (int i = tid; i < 51200; i += 512) {
        const int r = i / 50;
        const int c = i - r * 50;
        const float4 h4 = *(const float4*)(hb + (size_t)r * 200 + c * 4);
        const float4 b4 = *(const float4*)(hbar + c * 4);
        float4 o;
        o.x = h4.x * b4.x; o.y = h4.y * b4.y; o.z = h4.z * b4.z; o.w = h4.w * b4.w;
        *(float4*)(G + (size_t)(n * 1024 + r) * 800 + 600 + c * 4) = o;
    }
}

extern "C" void kernel_launch(void* const* d_in, const int* in_sizes, int n_in,
                              void* d_out, int out_size)
{
    const float* H      = (const float*)d_in[0];
    const float* U      = (const float*)d_in[1];
    const float* c_mask = (const float*)d_in[2];
    const float* q_mask = (const float*)d_in[3];
    const float* w      = (const float*)d_in[4];
    const float* b      = (const float*)d_in[5];
    float* G = (float*)d_out;

    cudaFuncSetAttribute(bi_attn_main, cudaFuncAttributeMaxDynamicSharedMemorySize, SMEM_BYTES);

    dim3 g1(8, 64);
    bi_attn_main<<<g1, 256, SMEM_BYTES>>>(H, U, q_mask, w, b, G);
    bi_attn_tail<<<64, 512>>>(H, c_mask, G);
}

// round 5
// speedup vs baseline: 1.3847x; 1.2279x over previous
#include <cuda_runtime.h>

// BiAttention (BiDAF): N=64, T=1024, J=64, D2=200.
// G = concat([H, U_, H*U_, H*H_], -1) -> (64, 1024, 800) fp32.

#define NEGV (-10000000.0f)

__device__ float g_Smax[64 * 1024];
__device__ float g_a[64 * 1024];
__device__ float g_part[64 * 8 * 200];

typedef unsigned long long ull;

// ---- shared layout (floats) ----
// Phase A:  sU raw U tile [64][204] at 0 ; sH scaled H half-tile [128][108] at 13056
// Between:  sUc chunk-major U [25 chunks][64 j][8 floats], stride 516 -> aliases sH
// Phase C:  sPs P [128][68] -> aliases sU (raw U dead after sUc copy)
#define SU   204
#define SXH  108
#define SPS  68
#define SUC_STRIDE 516
#define OFF_U    0
#define OFF_X    13056
#define OFF_HWH  26880
#define OFF_UWU  27008
#define OFF_QM   27072
#define OFF_W    27136
#define SMEM_FLOATS 27736
#define SMEM_BYTES  (SMEM_FLOATS * 4)   // 110944 -> 2 CTAs/SM

__device__ __forceinline__ void fma2(ull& acc, ull a, ull b) {
    asm("fma.rn.f32x2 %0, %1, %2, %0;" : "+l"(acc) : "l"(a), "l"(b));
}
__device__ __forceinline__ ull dup2(float x) {
    ull r; unsigned xi = __float_as_uint(x);
    asm("mov.b64 %0, {%1, %1};" : "=l"(r) : "r"(xi));
    return r;
}
__device__ __forceinline__ float lo32(ull v) { return __uint_as_float((unsigned)v); }
__device__ __forceinline__ float hi32(ull v) { return __uint_as_float((unsigned)(v >> 32)); }

union F4U2 { float4 f; ull u[2]; };

__global__ void __launch_bounds__(256, 2)
bi_attn_main(const float* __restrict__ H, const float* __restrict__ U,
             const float* __restrict__ q_mask, const float* __restrict__ wv,
             const float* __restrict__ bptr, float* __restrict__ G)
{
    extern __shared__ float sm[];
    float* sU   = sm + OFF_U;    // raw U (phases: staging + GEMM)
    float* sPs  = sm + OFF_U;    // ALIAS: P [128][68] (phase C)
    float* sH   = sm + OFF_X;    // scaled H half-tile (phase A)
    float* sUc  = sm + OFF_X;    // ALIAS: chunk-major U (phase C)
    float* sHwh = sm + OFF_HWH;
    float* sUwu = sm + OFF_UWU;
    float* sQm  = sm + OFF_QM;
    float* sW   = sm + OFF_W;

    const int tid = threadIdx.x;
    const int n   = blockIdx.y;
    const int m0  = blockIdx.x * 128;

    for (int i = tid; i < 600; i += 256) sW[i] = wv[i];
    if (tid < 64) sQm[tid] = q_mask[n * 64 + tid];
    __syncthreads();

    const float bval = bptr[0];

    // ---- stage U full + uwu : 4 lanes per j-row ----
    {
        const int j  = tid >> 2;
        const int kg = tid & 3;
        const float* urow = U + (size_t)(n * 64 + j) * 200;
        float uwu = 0.f;
        #pragma unroll
        for (int c = kg; c < 50; c += 4) {
            float4 u4  = *(const float4*)(urow + c * 4);
            float4 wu4 = *(const float4*)(sW + 200 + c * 4);
            uwu += u4.x * wu4.x + u4.y * wu4.y + u4.z * wu4.z + u4.w * wu4.w;
            *(float4*)(sU + j * SU + c * 4) = u4;
        }
        uwu += __shfl_xor_sync(0xffffffffu, uwu, 1);
        uwu += __shfl_xor_sync(0xffffffffu, uwu, 2);
        if (kg == 0) sUwu[j] = uwu;
    }

    // H staging: 2 lanes per row
    const int hrowi = tid >> 1;
    const int hkg   = tid & 1;
    const float* hrow = H + (size_t)(n * 1024 + m0 + hrowi) * 200;
    float hwh_acc = 0.f;

    // stage H half 0 (k in [0,100))
    #pragma unroll
    for (int c = hkg; c < 25; c += 2) {
        const int k = c * 4;
        float4 h4   = *(const float4*)(hrow + k);
        float4 wh4  = *(const float4*)(sW + k);
        float4 whu4 = *(const float4*)(sW + 400 + k);
        hwh_acc += h4.x * wh4.x + h4.y * wh4.y + h4.z * wh4.z + h4.w * wh4.w;
        float4 hs;
        hs.x = h4.x * whu4.x; hs.y = h4.y * whu4.y;
        hs.z = h4.z * whu4.z; hs.w = h4.w * whu4.w;
        *(float4*)(sH + hrowi * SXH + k) = hs;
    }
    __syncthreads();

    const int mg = tid >> 3;   // 0..31 -> rows mg*4 .. mg*4+3
    const int tj = tid & 7;    // 0..7  -> cols j = tj + 8*jj

    ull acc[4][8];
    #pragma unroll
    for (int i = 0; i < 4; i++)
        #pragma unroll
        for (int jj = 0; jj < 8; jj++) acc[i][jj] = 0ull;

    const float* aBase = sH + mg * 4 * SXH;
    const float* bBase = sU + tj * SU;

    // ---- GEMM half 0 ----
    #pragma unroll 1
    for (int kc = 0; kc < 25; kc++) {
        const int k = kc * 4;
        F4U2 a0, a1, a2, a3;
        a0.f = *(const float4*)(aBase + k);
        a1.f = *(const float4*)(aBase + SXH + k);
        a2.f = *(const float4*)(aBase + 2 * SXH + k);
        a3.f = *(const float4*)(aBase + 3 * SXH + k);
        #pragma unroll
        for (int g = 0; g < 2; g++) {
            F4U2 b[4];
            #pragma unroll
            for (int q = 0; q < 4; q++)
                b[q].f = *(const float4*)(bBase + (g * 4 + q) * (8 * SU) + k);
            #pragma unroll
            for (int q = 0; q < 4; q++) {
                const int jj = g * 4 + q;
                fma2(acc[0][jj], a0.u[0], b[q].u[0]); fma2(acc[0][jj], a0.u[1], b[q].u[1]);
                fma2(acc[1][jj], a1.u[0], b[q].u[0]); fma2(acc[1][jj], a1.u[1], b[q].u[1]);
                fma2(acc[2][jj], a2.u[0], b[q].u[0]); fma2(acc[2][jj], a2.u[1], b[q].u[1]);
                fma2(acc[3][jj], a3.u[0], b[q].u[0]); fma2(acc[3][jj], a3.u[1], b[q].u[1]);
            }
        }
    }
    __syncthreads();

    // stage H half 1 (k in [100,200)), finalize hwh
    #pragma unroll
    for (int c = hkg; c < 25; c += 2) {
        const int k = 100 + c * 4;
        float4 h4   = *(const float4*)(hrow + k);
        float4 wh4  = *(const float4*)(sW + k);
        float4 whu4 = *(const float4*)(sW + 400 + k);
        hwh_acc += h4.x * wh4.x + h4.y * wh4.y + h4.z * wh4.z + h4.w * wh4.w;
        float4 hs;
        hs.x = h4.x * whu4.x; hs.y = h4.y * whu4.y;
        hs.z = h4.z * whu4.z; hs.w = h4.w * whu4.w;
        *(float4*)(sH + hrowi * SXH + c * 4) = hs;
    }
    {
        float hv = hwh_acc + __shfl_xor_sync(0xffffffffu, hwh_acc, 1);
        if (hkg == 0) sHwh[hrowi] = hv;
    }
    __syncthreads();

    // ---- GEMM half 1 (B offset +100) ----
    #pragma unroll 1
    for (int kc = 0; kc < 25; kc++) {
        const int k = kc * 4;
        F4U2 a0, a1, a2, a3;
        a0.f = *(const float4*)(aBase + k);
        a1.f = *(const float4*)(aBase + SXH + k);
        a2.f = *(const float4*)(aBase + 2 * SXH + k);
        a3.f = *(const float4*)(aBase + 3 * SXH + k);
        #pragma unroll
        for (int g = 0; g < 2; g++) {
            F4U2 b[4];
            #pragma unroll
            for (int q = 0; q < 4; q++)
                b[q].f = *(const float4*)(bBase + 100 + (g * 4 + q) * (8 * SU) + k);
            #pragma unroll
            for (int q = 0; q < 4; q++) {
                const int jj = g * 4 + q;
                fma2(acc[0][jj], a0.u[0], b[q].u[0]); fma2(acc[0][jj], a0.u[1], b[q].u[1]);
                fma2(acc[1][jj], a1.u[0], b[q].u[0]); fma2(acc[1][jj], a1.u[1], b[q].u[1]);
                fma2(acc[2][jj], a2.u[0], b[q].u[0]); fma2(acc[2][jj], a2.u[1], b[q].u[1]);
                fma2(acc[3][jj], a3.u[0], b[q].u[0]); fma2(acc[3][jj], a3.u[1], b[q].u[1]);
            }
        }
    }
    __syncthreads();   // GEMM done: sH dead, sU still live (copy source)

    // ---- repack U chunk-major into sUc (conflict-free for phase C) ----
    #pragma unroll 1
    for (int idx = tid; idx < 1600; idx += 256) {
        const int chunk = idx >> 6;
        const int j     = idx & 63;
        const float4 vA = *(const float4*)(sU + j * SU + chunk * 8);
        const float4 vB = *(const float4*)(sU + j * SU + chunk * 8 + 4);
        *(float4*)(sUc + chunk * SUC_STRIDE + j * 8)     = vA;
        *(float4*)(sUc + chunk * SUC_STRIDE + j * 8 + 4) = vB;
    }

    // ---- softmax over j for 4 rows (registers only) ----
    float pv[4][8];
    #pragma unroll 1
    for (int i = 0; i < 4; i++) {
        const int m = mg * 4 + i;
        const float hwh = sHwh[m];
        float vmv[8], qv[8];
        float mx = -3.4e38f, smx = -3.4e38f;
        #pragma unroll
        for (int jj = 0; jj < 8; jj++) {
            const int j = tj + 8 * jj;
            const ull v = acc[i][jj];
            const float s = lo32(v) + hi32(v) + hwh + sUwu[j] + bval;
            const float q = sQm[j];
            const float vm = s * q;
            vmv[jj] = vm; qv[jj] = q;
            mx  = fmaxf(mx, vm);
            smx = fmaxf(smx, (q != 0.f) ? s : NEGV);
        }
        mx  = fmaxf(mx,  __shfl_xor_sync(0xffffffffu, mx, 1));
        mx  = fmaxf(mx,  __shfl_xor_sync(0xffffffffu, mx, 2));
        mx  = fmaxf(mx,  __shfl_xor_sync(0xffffffffu, mx, 4));
        smx = fmaxf(smx, __shfl_xor_sync(0xffffffffu, smx, 1));
        smx = fmaxf(smx, __shfl_xor_sync(0xffffffffu, smx, 2));
        smx = fmaxf(smx, __shfl_xor_sync(0xffffffffu, smx, 4));
        float E = 0.f, M = 0.f, ev[8];
        #pragma unroll
        for (int jj = 0; jj < 8; jj++) {
            const float e = __expf(vmv[jj] - mx);
            ev[jj] = e; E += e; M += e * qv[jj];
        }
        E += __shfl_xor_sync(0xffffffffu, E, 1);
        E += __shfl_xor_sync(0xffffffffu, E, 2);
        E += __shfl_xor_sync(0xffffffffu, E, 4);
        M += __shfl_xor_sync(0xffffffffu, M, 1);
        M += __shfl_xor_sync(0xffffffffu, M, 2);
        M += __shfl_xor_sync(0xffffffffu, M, 4);
        const float inv = 1.0f / (M + 1e-13f * E);
        #pragma unroll
        for (int jj = 0; jj < 8; jj++) pv[i][jj] = ev[jj] * qv[jj] * inv;
        if (tj == 0) g_Smax[(n << 10) + m0 + m] = smx;
    }
    __syncthreads();   // sUc complete; raw sU no longer needed

    // write P over old sU region
    #pragma unroll
    for (int i = 0; i < 4; i++) {
        const int m = mg * 4 + i;
        #pragma unroll
        for (int jj = 0; jj < 8; jj++)
            sPs[m * SPS + tj + 8 * jj] = pv[i][jj];
    }
    __syncthreads();

    // ---- Phase C: U_ = P @ U ; write G[:,:,0:600] ----
    const int rg = tid >> 4;        // 0..15 -> rows rg*8 .. rg*8+7
    const int dl = tid & 15;        // 0..15 -> chunk = pass*16 + dl
    const float* pRow = sPs + rg * 8 * SPS;
    const float* HrowC = H + (size_t)(n * 1024 + m0 + rg * 8) * 200;
    float*       GrowC = G + (size_t)(n * 1024 + m0 + rg * 8) * 800;

    #pragma unroll 1
    for (int p = 0; p < 2; p++) {
        const int chunk = p * 16 + dl;
        const bool valid = (chunk < 25);
        const int cs = valid ? chunk : 0;
        const int d0 = cs * 8;
        const float* uc = sUc + cs * SUC_STRIDE;

        ull acc2[8][4];
        #pragma unroll
        for (int r = 0; r < 8; r++)
            #pragma unroll
            for (int u = 0; u < 4; u++) acc2[r][u] = 0ull;

        #pragma unroll 1
        for (int j = 0; j < 64; j += 4) {
            float4 P[8];
            #pragma unroll
            for (int r = 0; r < 8; r++)
                P[r] = *(const float4*)(pRow + r * SPS + j);
            #pragma unroll
            for (int q = 0; q < 4; q++) {
                const float* up = uc + (j + q) * 8;
                F4U2 bA, bB;
                bA.f = *(const float4*)(up);
                bB.f = *(const float4*)(up + 4);
                const float* Pq = (const float*)P;
                #pragma unroll
                for (int r = 0; r < 8; r++) {
                    const ull d = dup2(Pq[r * 4 + q]);
                    fma2(acc2[r][0], d, bA.u[0]);
                    fma2(acc2[r][1], d, bA.u[1]);
                    fma2(acc2[r][2], d, bB.u[0]);
                    fma2(acc2[r][3], d, bB.u[1]);
                }
            }
        }

        if (valid) {
            #pragma unroll
            for (int r = 0; r < 8; r++) {
                float4 uA, uB;
                uA.x = lo32(acc2[r][0]); uA.y = hi32(acc2[r][0]);
                uA.z = lo32(acc2[r][1]); uA.w = hi32(acc2[r][1]);
                uB.x = lo32(acc2[r][2]); uB.y = hi32(acc2[r][2]);
                uB.z = lo32(acc2[r][3]); uB.w = hi32(acc2[r][3]);
                const float4 hA = *(const float4*)(HrowC + r * 200 + d0);
                const float4 hB = *(const float4*)(HrowC + r * 200 + d0 + 4);
                float* gp = GrowC + (size_t)r * 800;
                *(float4*)(gp + d0)           = hA;
                *(float4*)(gp + d0 + 4)       = hB;
                *(float4*)(gp + 200 + d0)     = uA;
                *(float4*)(gp + 200 + d0 + 4) = uB;
                float4 mA, mB;
                mA.x = hA.x * uA.x; mA.y = hA.y * uA.y; mA.z = hA.z * uA.z; mA.w = hA.w * uA.w;
                mB.x = hB.x * uB.x; mB.y = hB.y * uB.y; mB.z = hB.z * uB.z; mB.w = hB.w * uB.w;
                *(float4*)(gp + 400 + d0)     = mA;
                *(float4*)(gp + 400 + d0 + 4) = mB;
            }
        }
    }
}

// ---- tail 1: a = masked_softmax(S_max, c_mask) -> g_a ----
__global__ void __launch_bounds__(256)
tail_softmax(const float* __restrict__ c_mask)
{
    __shared__ float redA[8], redB[8], redC[8];
    const int n = blockIdx.x, tid = threadIdx.x;
    const int wid = tid >> 5, lane = tid & 31;

    float vm[4], cm[4];
    float mx = -3.4e38f;
    #pragma unroll
    for (int r = 0; r < 4; r++) {
        const int t = tid + 256 * r;
        const float c = c_mask[n * 1024 + t];
        const float v = g_Smax[n * 1024 + t] * c;
        vm[r] = v; cm[r] = c;
        mx = fmaxf(mx, v);
    }
    #pragma unroll
    for (int o = 16; o > 0; o >>= 1) mx = fmaxf(mx, __shfl_xor_sync(0xffffffffu, mx, o));
    if (lane == 0) redA[wid] = mx;
    __syncthreads();
    mx = redA[0];
    #pragma unroll
    for (int i = 1; i < 8; i++) mx = fmaxf(mx, redA[i]);

    float E = 0.f, M = 0.f, ev[4];
    #pragma unroll
    for (int r = 0; r < 4; r++) {
        const float e = __expf(vm[r] - mx);
        ev[r] = e; E += e; M += e * cm[r];
    }
    #pragma unroll
    for (int o = 16; o > 0; o >>= 1) {
        E += __shfl_xor_sync(0xffffffffu, E, o);
        M += __shfl_xor_sync(0xffffffffu, M, o);
    }
    if (lane == 0) { redB[wid] = E; redC[wid] = M; }
    __syncthreads();
    E = 0.f; M = 0.f;
    #pragma unroll
    for (int i = 0; i < 8; i++) { E += redB[i]; M += redC[i]; }
    const float inv = 1.0f / (M + 1e-13f * E);
    #pragma unroll
    for (int r = 0; r < 4; r++)
        g_a[n * 1024 + tid + 256 * r] = ev[r] * cm[r] * inv;
}

// ---- tail 2: partial Hbar over 128-t chunks -> g_part[n][s][200] ----
__global__ void __launch_bounds__(256)
tail_hbar(const float* __restrict__ H)
{
    __shared__ float sa[128];
    __shared__ float part[8][208];
    const int n = blockIdx.x, s = blockIdx.y, tid = threadIdx.x;
    const int wid = tid >> 5, lane = tid & 31;

    if (tid < 128) sa[tid] = g_a[n * 1024 + s * 128 + tid];
    __syncthreads();

    const int d0v = lane * 4;
    const int d1v = 128 + lane * 4;
    const bool v1 = (lane < 18);
    float4 a0 = {0.f, 0.f, 0.f, 0.f}, a1 = {0.f, 0.f, 0.f, 0.f};
    const float* hb = H + (size_t)n * 204800 + (size_t)s * 128 * 200;
    #pragma unroll 4
    for (int t = wid * 16; t < wid * 16 + 16; t++) {
        const float av = sa[t];
        const float* hr = hb + (size_t)t * 200;
        const float4 h0 = *(const float4*)(hr + d0v);
        a0.x += av * h0.x; a0.y += av * h0.y; a0.z += av * h0.z; a0.w += av * h0.w;
        if (v1) {
            const float4 h1 = *(const float4*)(hr + d1v);
            a1.x += av * h1.x; a1.y += av * h1.y; a1.z += av * h1.z; a1.w += av * h1.w;
        }
    }
    *(float4*)(&part[wid][d0v]) = a0;
    if (v1) *(float4*)(&part[wid][d1v]) = a1;
    __syncthreads();

    if (tid < 200) {
        float sum = 0.f;
        #pragma unroll
        for (int w = 0; w < 8; w++) sum += part[w][tid];
        g_part[(n * 8 + s) * 200 + tid] = sum;
    }
}

// ---- tail 3: reduce partials + G[:,:,600:800] = H * Hbar ----
__global__ void __launch_bounds__(512)
tail_prod(const float* __restrict__ H, float* __restrict__ G)
{
    __shared__ float hbar[200];
    const int n = blockIdx.x, s = blockIdx.y, tid = threadIdx.x;

    if (tid < 200) {
        float sum = 0.f;
        #pragma unroll
        for (int w = 0; w < 8; w++) sum += g_part[(n * 8 + w) * 200 + tid];
        hbar[tid] = sum;
    }
    __syncthreads();

    const float* hb = H + (size_t)n * 204800 + (size_t)s * 128 * 200;
    float* gb = G + (size_t)(n * 1024 + s * 128) * 800;
    #pragma unroll 1
    for (int i = tid; i < 6400; i += 512) {
        const int r = i / 50;
        const int c = i - r * 50;
        const float4 h4 = *(const float4*)(hb + (size_t)r * 200 + c * 4);
        const float4 b4 = *(const float4*)(hbar + c * 4);
        float4 o;
        o.x = h4.x * b4.x; o.y = h4.y * b4.y; o.z = h4.z * b4.z; o.w = h4.w * b4.w;
        *(float4*)(gb + (size_t)r * 800 + 600 + c * 4) = o;
    }
}

extern "C" void kernel_launch(void* const* d_in, const int* in_sizes, int n_in,
                              void* d_out, int out_size)
{
    const float* H      = (const float*)d_in[0];
    const float* U      = (const float*)d_in[1];
    const float* c_mask = (const float*)d_in[2];
    const float* q_mask = (const float*)d_in[3];
    const float* w      = (const float*)d_in[4];
    const float* b      = (const float*)d_in[5];
    float* G = (float*)d_out;

    cudaFuncSetAttribute(bi_attn_main, cudaFuncAttributeMaxDynamicSharedMemorySize, SMEM_BYTES);

    dim3 g1(8, 64);
    bi_attn_main<<<g1, 256, SMEM_BYTES>>>(H, U, q_mask, w, b, G);
    tail_softmax<<<64, 256>>>(c_mask);
    dim3 g3(64, 8);
    tail_hbar<<<g3, 256>>>(H);
    tail_prod<<<g3, 512>>>(H, G);
}